// round 11
// baseline (speedup 1.0000x reference)
#include <cuda_runtime.h>
#include <cuda_bf16.h>
#include <cuda_fp16.h>
#include <math.h>
#include <stdint.h>

#define BATCH 8
#define CH    256
#define NPIX  4096
#define NBLK  32            // NPIX / 128 score blocks per row

// Packed split formats: u32 = lo16(hi) | lo16(lo)<<16, value ~= hi + lo
static __device__ uint32_t g_wp[3 * CH * CH];                  // packed bf16 wq|wk|wv
static __device__ uint32_t g_xt[(size_t)BATCH * NPIX * CH];    // x^T  [b][n][c] bf16-split
static __device__ uint32_t g_qt[(size_t)BATCH * NPIX * CH];    // Q^T  [b][n][c] bf16-split
static __device__ uint32_t g_kt[(size_t)BATCH * NPIX * CH];    // K^T  [b][n][c] bf16-split
static __device__ __half   g_vh[(size_t)BATCH * CH * NPIX];    // V    [b][c][n] fp16 single
static __device__ __half   g_ah[(size_t)BATCH * NPIX * NPIX];  // p / attn fp16 [b][i][j]
static __device__ float    g_bm[(size_t)BATCH * NBLK * NPIX];  // block row max [b][jb][i]
static __device__ float    g_bl[(size_t)BATCH * NBLK * NPIX];  // block row sum [b][jb][i]
static __device__ float    g_sc[(size_t)BATCH * NBLK * NPIX];  // scale [b][jb][i]

__device__ __forceinline__ uint32_t smem_u32(const void* p) {
    uint32_t a;
    asm("{ .reg .u64 t; cvta.to.shared.u64 t, %1; cvt.u32.u64 %0, t; }" : "=r"(a) : "l"(p));
    return a;
}
__device__ __forceinline__ uint32_t pack_split(float v) {         // bf16 hi+lo
    __nv_bfloat16 h = __float2bfloat16(v);
    float r = v - __bfloat162float(h);
    __nv_bfloat16 l = __float2bfloat16(r);
    return (uint32_t)__bfloat16_as_ushort(h) | ((uint32_t)__bfloat16_as_ushort(l) << 16);
}
__device__ __forceinline__ void cp16(uint32_t saddr, const void* g) {
    uint64_t ga;
    asm("cvta.to.global.u64 %0, %1;" : "=l"(ga) : "l"(g));
    asm volatile("cp.async.cg.shared.global [%0], [%1], 16;" :: "r"(saddr), "l"(ga));
}
#define CP_COMMIT() asm volatile("cp.async.commit_group;" ::: "memory")
#define CP_WAIT1()  asm volatile("cp.async.wait_group 1;"  ::: "memory")
#define CP_WAIT0()  asm volatile("cp.async.wait_group 0;"  ::: "memory")
#define LDS64(a, b, addr) \
    asm volatile("ld.shared.v2.u32 {%0,%1}, [%2];" : "=r"(a), "=r"(b) : "r"(addr))
#define LDS32(a, addr) \
    asm volatile("ld.shared.u32 %0, [%1];" : "=r"(a) : "r"(addr))
#define MMAB(d, a, b0, b1)                                                        \
    asm volatile("mma.sync.aligned.m16n8k16.row.col.f32.bf16.bf16.f32 "           \
        "{%0,%1,%2,%3}, {%4,%5,%6,%7}, {%8,%9}, {%0,%1,%2,%3};"                   \
        : "+f"((d)[0]), "+f"((d)[1]), "+f"((d)[2]), "+f"((d)[3])                  \
        : "r"((a)[0]), "r"((a)[1]), "r"((a)[2]), "r"((a)[3]), "r"(b0), "r"(b1))
#define MMAH(d, a, b0, b1)                                                        \
    asm volatile("mma.sync.aligned.m16n8k16.row.col.f32.f16.f16.f32 "             \
        "{%0,%1,%2,%3}, {%4,%5,%6,%7}, {%8,%9}, {%0,%1,%2,%3};"                   \
        : "+f"((d)[0]), "+f"((d)[1]), "+f"((d)[2]), "+f"((d)[3])                  \
        : "r"((a)[0]), "r"((a)[1]), "r"((a)[2]), "r"((a)[3]), "r"(b0), "r"(b1))

// ---------------------------------------------------------------------------
// QKV GEMM (proven): packed split-bf16, 3-MMA. CTA 128x256, 1 CTA/SM.
// MODE: 1 = packed bf16-split out + bias[col]; 2 = fp16 single out + bias[row]
// ---------------------------------------------------------------------------
#define BM 128
#define BN 256
#define BK 32
#define A_U32S  (BM * 40)
#define B_U32S  (BN * 40)
#define A_BYTES (A_U32S * 4)
#define BUF_BYTES ((A_U32S + B_U32S) * 4)   // 61440
#define GEMM_SMEM (3 * BUF_BYTES)           // 184320

__device__ __forceinline__ void load_tiles(const uint32_t* __restrict__ Ag, int lda,
                                           const uint32_t* __restrict__ Bg, int ldb,
                                           uint32_t sbase, int tid) {
    #pragma unroll
    for (int i = 0; i < 4; i++) {
        int t = i * 256 + tid;
        int row = t >> 3, q = t & 7;
        cp16(sbase + (uint32_t)(row * 40 + q * 4) * 4, Ag + (size_t)row * lda + q * 4);
    }
    #pragma unroll
    for (int i = 0; i < 8; i++) {
        int t = i * 256 + tid;
        int row = t >> 3, q = t & 7;
        cp16(sbase + A_BYTES + (uint32_t)(row * 40 + q * 4) * 4, Bg + (size_t)row * ldb + q * 4);
    }
}

__device__ __forceinline__ void compute_tile(uint32_t sa, int lane, int wm, int wn,
                                             float (&acc)[4][8][4]) {
    uint32_t sb = sa + A_BYTES;
    #pragma unroll
    for (int ks = 0; ks < 2; ks++) {
        const int kc = ks * 16 + (lane & 3) * 2;
        uint32_t ah[4][4], al[4][4];
        #pragma unroll
        for (int mt = 0; mt < 4; mt++) {
            int r = wm * 64 + mt * 16 + (lane >> 2);
            uint32_t x0, x1, y0, y1, x2, x3, y2, y3;
            LDS64(x0, x1, sa + (uint32_t)(r * 40 + kc) * 4);
            LDS64(y0, y1, sa + (uint32_t)((r + 8) * 40 + kc) * 4);
            LDS64(x2, x3, sa + (uint32_t)(r * 40 + kc + 8) * 4);
            LDS64(y2, y3, sa + (uint32_t)((r + 8) * 40 + kc + 8) * 4);
            ah[mt][0] = __byte_perm(x0, x1, 0x5410); al[mt][0] = __byte_perm(x0, x1, 0x7632);
            ah[mt][1] = __byte_perm(y0, y1, 0x5410); al[mt][1] = __byte_perm(y0, y1, 0x7632);
            ah[mt][2] = __byte_perm(x2, x3, 0x5410); al[mt][2] = __byte_perm(x2, x3, 0x7632);
            ah[mt][3] = __byte_perm(y2, y3, 0x5410); al[mt][3] = __byte_perm(y2, y3, 0x7632);
        }
        #pragma unroll
        for (int nt = 0; nt < 8; nt++) {
            int r = wn * 64 + nt * 8 + (lane >> 2);
            uint32_t u0, u1, u2, u3;
            LDS64(u0, u1, sb + (uint32_t)(r * 40 + kc) * 4);
            LDS64(u2, u3, sb + (uint32_t)(r * 40 + kc + 8) * 4);
            uint32_t bh0 = __byte_perm(u0, u1, 0x5410), bh1 = __byte_perm(u2, u3, 0x5410);
            uint32_t bl0 = __byte_perm(u0, u1, 0x7632), bl1 = __byte_perm(u2, u3, 0x7632);
            #pragma unroll
            for (int mt = 0; mt < 4; mt++) {
                MMAB(acc[mt][nt], ah[mt], bh0, bh1);
                MMAB(acc[mt][nt], ah[mt], bl0, bl1);
                MMAB(acc[mt][nt], al[mt], bh0, bh1);
            }
        }
    }
}

template<int MODE>
__global__ __launch_bounds__(256)
void gemm_kernel(const uint32_t* __restrict__ A, int lda, size_t sA,
                 const uint32_t* __restrict__ B, int ldb, size_t sB,
                 void* __restrict__ Dv, int ldd, size_t sD,
                 const float* __restrict__ bias, int K)
{
    extern __shared__ __align__(16) uint32_t smraw[];
    const uint32_t smbase = smem_u32(smraw);
    const int tid = threadIdx.x;
    const int lane = tid & 31, wid = tid >> 5;
    const int wm = wid >> 2, wn = wid & 3;
    const int z = blockIdx.z;
    const int bm = blockIdx.y * BM, bn = blockIdx.x * BN;

    A += (size_t)z * sA + (size_t)bm * lda;
    B += (size_t)z * sB + (size_t)bn * ldb;

    float acc[4][8][4];
    #pragma unroll
    for (int i = 0; i < 4; i++)
        #pragma unroll
        for (int j = 0; j < 8; j++)
            #pragma unroll
            for (int v = 0; v < 4; v++) acc[i][j][v] = 0.f;

    const int S = K / BK;
    load_tiles(A, lda, B, ldb, smbase, tid);
    CP_COMMIT();
    load_tiles(A + BK, lda, B + BK, ldb, smbase + BUF_BYTES, tid);
    CP_COMMIT();

    #pragma unroll 1
    for (int s = 0; s < S; s++) {
        CP_WAIT1();
        __syncthreads();
        if (s + 2 < S)
            load_tiles(A + (s + 2) * BK, lda, B + (s + 2) * BK, ldb,
                       smbase + (uint32_t)((s + 2) % 3) * BUF_BYTES, tid);
        CP_COMMIT();
        compute_tile(smbase + (uint32_t)(s % 3) * BUF_BYTES, lane, wm, wn, acc);
    }

    #pragma unroll
    for (int nt = 0; nt < 8; nt++) {
        int col = bn + wn * 64 + nt * 8 + (lane & 3) * 2;
        float bc0 = 0.f, bc1 = 0.f;
        if (MODE == 1) { bc0 = bias[col]; bc1 = bias[col + 1]; }
        #pragma unroll
        for (int mt = 0; mt < 4; mt++) {
            int r0 = bm + wm * 64 + mt * 16 + (lane >> 2);
            if (MODE == 1) {
                uint32_t* D = (uint32_t*)Dv + (size_t)z * sD;
                uint32_t p0 = pack_split(acc[mt][nt][0] + bc0);
                uint32_t p1 = pack_split(acc[mt][nt][1] + bc1);
                uint32_t p2 = pack_split(acc[mt][nt][2] + bc0);
                uint32_t p3 = pack_split(acc[mt][nt][3] + bc1);
                *(uint2*)&D[(size_t)r0 * ldd + col] = make_uint2(p0, p1);
                *(uint2*)&D[(size_t)(r0 + 8) * ldd + col] = make_uint2(p2, p3);
            } else {
                __half* D = (__half*)Dv + (size_t)z * sD;
                float b0 = bias[r0], b8 = bias[r0 + 8];
                __half2 v01 = __floats2half2_rn(acc[mt][nt][0] + b0, acc[mt][nt][1] + b0);
                __half2 v23 = __floats2half2_rn(acc[mt][nt][2] + b8, acc[mt][nt][3] + b8);
                *(__half2*)&D[(size_t)r0 * ldd + col] = v01;
                *(__half2*)&D[(size_t)(r0 + 8) * ldd + col] = v23;
            }
        }
    }
}

// ---------------------------------------------------------------------------
// Scores GEMM with fused block-softmax epilogue. 2 CTAs/SM, CTA 128x128,
// warp tile 64x32. Emits p = exp(s - m_block) fp16, plus m_block/l_block.
// ---------------------------------------------------------------------------
#define S2TILE 20480                        // 128 rows * 40 u32 * 4B
#define S2BUF  (2 * S2TILE)                 // 40960
#define S2RED  (2 * S2BUF)                  // 81920 : red arrays (2 x 2KB)
#define S2SMEM (S2RED + 4096)               // 86016

__device__ __forceinline__ void load_s2(const uint32_t* __restrict__ Ag,
                                        const uint32_t* __restrict__ Bg,
                                        uint32_t sbase, int tid) {
    #pragma unroll
    for (int i = 0; i < 4; i++) {
        int t = i * 256 + tid;
        int row = t >> 3, q = t & 7;
        cp16(sbase + (uint32_t)(row * 40 + q * 4) * 4, Ag + (size_t)row * CH + q * 4);
    }
    #pragma unroll
    for (int i = 0; i < 4; i++) {
        int t = i * 256 + tid;
        int row = t >> 3, q = t & 7;
        cp16(sbase + S2TILE + (uint32_t)(row * 40 + q * 4) * 4, Bg + (size_t)row * CH + q * 4);
    }
}

__global__ __launch_bounds__(256, 2)
void scores2_kernel()
{
    extern __shared__ __align__(16) uint32_t smraw[];
    const uint32_t smbase = smem_u32(smraw);
    const int tid = threadIdx.x;
    const int lane = tid & 31, wid = tid >> 5;
    const int wm = wid >> 2, wn = wid & 3;
    const int z = blockIdx.z;
    const int bm = blockIdx.y * 128, bn = blockIdx.x * 128;
    const int jb = blockIdx.x;

    const uint32_t* A = g_qt + (size_t)z * NPIX * CH + (size_t)bm * CH;
    const uint32_t* B = g_kt + (size_t)z * NPIX * CH + (size_t)bn * CH;

    float acc[4][4][4];
    #pragma unroll
    for (int i = 0; i < 4; i++)
        #pragma unroll
        for (int j = 0; j < 4; j++)
            #pragma unroll
            for (int v = 0; v < 4; v++) acc[i][j][v] = 0.f;

    const int qrow = lane >> 2, qcol = lane & 3;
    const int S = CH / BK;   // 8

    load_s2(A, B, smbase, tid);
    CP_COMMIT();

    #pragma unroll 1
    for (int s = 0; s < S; s++) {
        __syncthreads();
        if (s + 1 < S) {
            load_s2(A + (s + 1) * BK, B + (s + 1) * BK,
                    smbase + (uint32_t)((s + 1) & 1) * S2BUF, tid);
            CP_COMMIT();
            CP_WAIT1();
        } else {
            CP_WAIT0();
        }
        __syncthreads();
        uint32_t sa = smbase + (uint32_t)(s & 1) * S2BUF;
        uint32_t sb = sa + S2TILE;
        #pragma unroll
        for (int ks = 0; ks < 2; ks++) {
            const int kc = ks * 16 + qcol * 2;
            uint32_t ah[4][4], al[4][4];
            #pragma unroll
            for (int mt = 0; mt < 4; mt++) {
                int r = wm * 64 + mt * 16 + qrow;
                uint32_t x0, x1, y0, y1, x2, x3, y2, y3;
                LDS64(x0, x1, sa + (uint32_t)(r * 40 + kc) * 4);
                LDS64(y0, y1, sa + (uint32_t)((r + 8) * 40 + kc) * 4);
                LDS64(x2, x3, sa + (uint32_t)(r * 40 + kc + 8) * 4);
                LDS64(y2, y3, sa + (uint32_t)((r + 8) * 40 + kc + 8) * 4);
                ah[mt][0] = __byte_perm(x0, x1, 0x5410); al[mt][0] = __byte_perm(x0, x1, 0x7632);
                ah[mt][1] = __byte_perm(y0, y1, 0x5410); al[mt][1] = __byte_perm(y0, y1, 0x7632);
                ah[mt][2] = __byte_perm(x2, x3, 0x5410); al[mt][2] = __byte_perm(x2, x3, 0x7632);
                ah[mt][3] = __byte_perm(y2, y3, 0x5410); al[mt][3] = __byte_perm(y2, y3, 0x7632);
            }
            #pragma unroll
            for (int nt = 0; nt < 4; nt++) {
                int r = wn * 32 + nt * 8 + qrow;
                uint32_t u0, u1, u2, u3;
                LDS64(u0, u1, sb + (uint32_t)(r * 40 + kc) * 4);
                LDS64(u2, u3, sb + (uint32_t)(r * 40 + kc + 8) * 4);
                uint32_t bh0 = __byte_perm(u0, u1, 0x5410), bh1 = __byte_perm(u2, u3, 0x5410);
                uint32_t bl0 = __byte_perm(u0, u1, 0x7632), bl1 = __byte_perm(u2, u3, 0x7632);
                #pragma unroll
                for (int mt = 0; mt < 4; mt++) {
                    MMAB(acc[mt][nt], ah[mt], bh0, bh1);
                    MMAB(acc[mt][nt], ah[mt], bl0, bl1);
                    MMAB(acc[mt][nt], al[mt], bh0, bh1);
                }
            }
        }
    }

    // ---- fused block-softmax epilogue ----
    float* redm = (float*)smraw + (S2RED >> 2);          // [4][128]
    float* redl = redm + 512;                            // [4][128]

    // warp-level row max over this warp's 32 cols
    float mrow[4][2];
    #pragma unroll
    for (int mt = 0; mt < 4; mt++)
        #pragma unroll
        for (int h = 0; h < 2; h++) {
            float v = -1e30f;
            #pragma unroll
            for (int nt = 0; nt < 4; nt++)
                v = fmaxf(v, fmaxf(acc[mt][nt][h * 2], acc[mt][nt][h * 2 + 1]));
            v = fmaxf(v, __shfl_xor_sync(0xffffffffu, v, 1));
            v = fmaxf(v, __shfl_xor_sync(0xffffffffu, v, 2));
            mrow[mt][h] = v;
            if (qcol == 0)
                redm[wn * 128 + wm * 64 + mt * 16 + qrow + h * 8] = v;
        }
    __syncthreads();
    // block row max (over 4 wn warps)
    #pragma unroll
    for (int mt = 0; mt < 4; mt++)
        #pragma unroll
        for (int h = 0; h < 2; h++) {
            int lr = wm * 64 + mt * 16 + qrow + h * 8;
            mrow[mt][h] = fmaxf(fmaxf(redm[lr], redm[128 + lr]),
                                fmaxf(redm[256 + lr], redm[384 + lr]));
        }

    // p = exp(s - m_block) -> fp16, accumulate row sums
    __half* Pb = g_ah + (size_t)z * NPIX * NPIX;
    float ls[4][2] = {{0.f,0.f},{0.f,0.f},{0.f,0.f},{0.f,0.f}};
    #pragma unroll
    for (int nt = 0; nt < 4; nt++) {
        int colg = bn + wn * 32 + nt * 8 + qcol * 2;
        #pragma unroll
        for (int mt = 0; mt < 4; mt++) {
            int r0 = bm + wm * 64 + mt * 16 + qrow;
            float p0 = __expf(acc[mt][nt][0] - mrow[mt][0]);
            float p1 = __expf(acc[mt][nt][1] - mrow[mt][0]);
            float p2 = __expf(acc[mt][nt][2] - mrow[mt][1]);
            float p3 = __expf(acc[mt][nt][3] - mrow[mt][1]);
            ls[mt][0] += p0 + p1;
            ls[mt][1] += p2 + p3;
            *(__half2*)&Pb[(size_t)r0 * NPIX + colg]       = __floats2half2_rn(p0, p1);
            *(__half2*)&Pb[(size_t)(r0 + 8) * NPIX + colg] = __floats2half2_rn(p2, p3);
        }
    }
    // row-sum reduce: quad shfl, then cross-warp via smem
    #pragma unroll
    for (int mt = 0; mt < 4; mt++)
        #pragma unroll
        for (int h = 0; h < 2; h++) {
            float v = ls[mt][h];
            v += __shfl_xor_sync(0xffffffffu, v, 1);
            v += __shfl_xor_sync(0xffffffffu, v, 2);
            if (qcol == 0)
                redl[wn * 128 + wm * 64 + mt * 16 + qrow + h * 8] = v;
        }
    __syncthreads();
    if (wn == 0 && qcol == 0) {
        float* BM_ = g_bm + ((size_t)z * NBLK + jb) * NPIX + bm;
        float* BL_ = g_bl + ((size_t)z * NBLK + jb) * NPIX + bm;
        #pragma unroll
        for (int mt = 0; mt < 4; mt++)
            #pragma unroll
            for (int h = 0; h < 2; h++) {
                int lr = wm * 64 + mt * 16 + qrow + h * 8;
                BM_[lr] = mrow[mt][h];
                BL_[lr] = redl[lr] + redl[128 + lr] + redl[256 + lr] + redl[384 + lr];
            }
    }
}

// ---------------------------------------------------------------------------
// Row stats: scale[z][jb][i] = exp(m_b - m_g) / tot
// ---------------------------------------------------------------------------
__global__ __launch_bounds__(256) void rowstats_kernel()
{
    int t = blockIdx.x * 256 + threadIdx.x;    // 0..32767
    int z = t >> 12, i = t & (NPIX - 1);
    size_t base = (size_t)z * NBLK * NPIX + i;

    float mv[NBLK];
    float mg = -1e30f;
    #pragma unroll
    for (int jb = 0; jb < NBLK; jb++) {
        mv[jb] = g_bm[base + (size_t)jb * NPIX];
        mg = fmaxf(mg, mv[jb]);
    }
    float tot = 0.f;
    #pragma unroll
    for (int jb = 0; jb < NBLK; jb++)
        tot += g_bl[base + (size_t)jb * NPIX] * __expf(mv[jb] - mg);
    float inv = 1.0f / tot;
    #pragma unroll
    for (int jb = 0; jb < NBLK; jb++)
        g_sc[base + (size_t)jb * NPIX] = __expf(mv[jb] - mg) * inv;
}

// ---------------------------------------------------------------------------
// Normalize: attn[i][j] = p[i][j] * scale[jblk][i], in place on g_ah.
// One block per (z, i) row.
// ---------------------------------------------------------------------------
__global__ __launch_bounds__(256) void norm_kernel()
{
    const int z = blockIdx.x >> 12, i = blockIdx.x & (NPIX - 1);
    const int tid = threadIdx.x;
    __shared__ float sscale[NBLK];
    if (tid < NBLK)
        sscale[tid] = g_sc[((size_t)z * NBLK + tid) * NPIX + i];
    __syncthreads();

    __half2* row = (__half2*)(g_ah + ((size_t)z * NPIX + i) * NPIX);
    #pragma unroll
    for (int k = 0; k < 8; k++) {
        int idx = tid + 256 * k;               // half2 index, col = 2*idx
        float s = sscale[idx >> 6];
        __half2 p = row[idx];
        float2 pf = __half22float2(p);
        row[idx] = __floats2half2_rn(pf.x * s, pf.y * s);
    }
}

// ---------------------------------------------------------------------------
// AV GEMM, 2 CTAs/SM (R10-proven): CTA 128(c)x128(i), single fp16 MMA pass.
// ---------------------------------------------------------------------------
#define AVTILE 10240
#define AVBUF  (2 * AVTILE)
#define AVSMEM (3 * AVBUF)

__device__ __forceinline__ void load_av2(const __half* __restrict__ Ag,
                                         const __half* __restrict__ Bg,
                                         uint32_t sbase, int tid) {
    #pragma unroll
    for (int i = 0; i < 2; i++) {
        int t = i * 256 + tid;
        int row = t >> 2, q = t & 3;
        cp16(sbase + (uint32_t)(row * 80 + q * 16), Ag + (size_t)row * NPIX + q * 8);
    }
    #pragma unroll
    for (int i = 0; i < 2; i++) {
        int t = i * 256 + tid;
        int row = t >> 2, q = t & 3;
        cp16(sbase + AVTILE + (uint32_t)(row * 80 + q * 16), Bg + (size_t)row * NPIX + q * 8);
    }
}

__global__ __launch_bounds__(256, 2)
void av2_kernel(const __half* __restrict__ A,
                const __half* __restrict__ B,
                float* __restrict__ D)
{
    extern __shared__ __align__(16) uint32_t smraw[];
    const uint32_t smbase = smem_u32(smraw);
    const int tid = threadIdx.x;
    const int lane = tid & 31, wid = tid >> 5;
    const int wm = wid >> 2, wn = wid & 3;
    const int z = blockIdx.z;
    const int bm = blockIdx.y * 128, bn = blockIdx.x * 128;

    A += (size_t)z * CH * NPIX + (size_t)bm * NPIX;
    B += (size_t)z * NPIX * NPIX + (size_t)bn * NPIX;
    D += (size_t)z * CH * NPIX;

    float acc[4][4][4];
    #pragma unroll
    for (int i = 0; i < 4; i++)
        #pragma unroll
        for (int j = 0; j < 4; j++)
            #pragma unroll
            for (int v = 0; v < 4; v++) acc[i][j][v] = 0.f;

    const int qrow = lane >> 2, qcol = lane & 3;
    const int S = NPIX / BK;   // 128

    load_av2(A, B, smbase, tid);
    CP_COMMIT();
    load_av2(A + BK, B + BK, smbase + AVBUF, tid);
    CP_COMMIT();

    #pragma unroll 1
    for (int s = 0; s < S; s++) {
        CP_WAIT1();
        __syncthreads();
        if (s + 2 < S)
            load_av2(A + (s + 2) * BK, B + (s + 2) * BK,
                     smbase + (uint32_t)((s + 2) % 3) * AVBUF, tid);
        CP_COMMIT();

        uint32_t sa = smbase + (uint32_t)(s % 3) * AVBUF;
        uint32_t sb = sa + AVTILE;
        #pragma unroll
        for (int ks = 0; ks < 2; ks++) {
            const int kc = ks * 16 + qcol * 2;
            uint32_t af[4][4];
            #pragma unroll
            for (int mt = 0; mt < 4; mt++) {
                int r = wm * 64 + mt * 16 + qrow;
                LDS32(af[mt][0], sa + (uint32_t)(r * 80 + kc * 2));
                LDS32(af[mt][1], sa + (uint32_t)((r + 8) * 80 + kc * 2));
                LDS32(af[mt][2], sa + (uint32_t)(r * 80 + (kc + 8) * 2));
                LDS32(af[mt][3], sa + (uint32_t)((r + 8) * 80 + (kc + 8) * 2));
            }
            #pragma unroll
            for (int nt = 0; nt < 4; nt++) {
                int cr = wn * 32 + nt * 8 + qrow;
                uint32_t b0, b1;
                LDS32(b0, sb + (uint32_t)(cr * 80 + kc * 2));
                LDS32(b1, sb + (uint32_t)(cr * 80 + (kc + 8) * 2));
                #pragma unroll
                for (int mt = 0; mt < 4; mt++)
                    MMAH(acc[mt][nt], af[mt], b0, b1);
            }
        }
    }

    #pragma unroll
    for (int nt = 0; nt < 4; nt++) {
        int col = bn + wn * 32 + nt * 8 + qcol * 2;
        #pragma unroll
        for (int mt = 0; mt < 4; mt++) {
            int r0 = bm + wm * 64 + mt * 16 + qrow;
            *(float2*)&D[(size_t)r0 * NPIX + col] =
                make_float2(acc[mt][nt][0], acc[mt][nt][1]);
            *(float2*)&D[(size_t)(r0 + 8) * NPIX + col] =
                make_float2(acc[mt][nt][2], acc[mt][nt][3]);
        }
    }
}

// ---------------------------------------------------------------------------
// Packing kernels
// ---------------------------------------------------------------------------
__global__ __launch_bounds__(256) void pack_w_kernel(
    const float* __restrict__ wq, const float* __restrict__ wk,
    const float* __restrict__ wv)
{
    int i = blockIdx.x * 256 + threadIdx.x;
    g_wp[i]               = pack_split(wq[i]);
    g_wp[CH * CH + i]     = pack_split(wk[i]);
    g_wp[2 * CH * CH + i] = pack_split(wv[i]);
}

__global__ __launch_bounds__(256) void pack_xt_kernel(const float* __restrict__ x)
{
    __shared__ float t[32][33];
    const int b = blockIdx.z;
    const int n0 = blockIdx.x * 32, c0 = blockIdx.y * 32;
    const int tx = threadIdx.x, ty = threadIdx.y;   // 32 x 8
    const float* xb = x + (size_t)b * CH * NPIX;
    #pragma unroll
    for (int i = 0; i < 4; i++)
        t[ty * 4 + i][tx] = xb[(size_t)(c0 + ty * 4 + i) * NPIX + n0 + tx];
    __syncthreads();
    uint32_t* xt = g_xt + (size_t)b * NPIX * CH;
    #pragma unroll
    for (int i = 0; i < 4; i++)
        xt[(size_t)(n0 + ty * 4 + i) * CH + c0 + tx] = pack_split(t[tx][ty * 4 + i]);
}

// ---------------------------------------------------------------------------
extern "C" void kernel_launch(void* const* d_in, const int* in_sizes, int n_in,
                              void* d_out, int out_size)
{
    const float* x  = (const float*)d_in[0];
    const float* wq = (const float*)d_in[1];
    const float* bq = (const float*)d_in[2];
    const float* wk = (const float*)d_in[3];
    const float* bk = (const float*)d_in[4];
    const float* wv = (const float*)d_in[5];
    const float* bv = (const float*)d_in[6];
    float* out = (float*)d_out;

    void *pwp, *pxt, *pqt, *pkt, *pvh, *pah;
    cudaGetSymbolAddress(&pwp, g_wp);
    cudaGetSymbolAddress(&pxt, g_xt);
    cudaGetSymbolAddress(&pqt, g_qt);
    cudaGetSymbolAddress(&pkt, g_kt);
    cudaGetSymbolAddress(&pvh, g_vh);
    cudaGetSymbolAddress(&pah, g_ah);
    uint32_t* wp = (uint32_t*)pwp;
    uint32_t* xt = (uint32_t*)pxt;
    uint32_t* qt = (uint32_t*)pqt;
    uint32_t* kt = (uint32_t*)pkt;
    __half*   vh = (__half*)pvh;
    __half*   ah = (__half*)pah;

    cudaFuncSetAttribute(gemm_kernel<1>, cudaFuncAttributeMaxDynamicSharedMemorySize, GEMM_SMEM);
    cudaFuncSetAttribute(gemm_kernel<2>, cudaFuncAttributeMaxDynamicSharedMemorySize, GEMM_SMEM);
    cudaFuncSetAttribute(scores2_kernel, cudaFuncAttributeMaxDynamicSharedMemorySize, S2SMEM);
    cudaFuncSetAttribute(av2_kernel,     cudaFuncAttributeMaxDynamicSharedMemorySize, AVSMEM);

    pack_w_kernel<<<CH * CH / 256, 256>>>(wq, wk, wv);
    pack_xt_kernel<<<dim3(NPIX / 32, CH / 32, BATCH), dim3(32, 8)>>>(x);

    // Q^T[n][c] = X^T[n][k] * Wq[c][k]^T + bq
    gemm_kernel<1><<<dim3(1, 32, BATCH), 256, GEMM_SMEM>>>(
        xt, CH, (size_t)NPIX * CH, wp, CH, 0,
        qt, CH, (size_t)NPIX * CH, bq, CH);
    gemm_kernel<1><<<dim3(1, 32, BATCH), 256, GEMM_SMEM>>>(
        xt, CH, (size_t)NPIX * CH, wp + CH * CH, CH, 0,
        kt, CH, (size_t)NPIX * CH, bk, CH);
    // V[c][n] fp16 single plane
    gemm_kernel<2><<<dim3(NPIX / BN, CH / BM, BATCH), 256, GEMM_SMEM>>>(
        wp + 2 * CH * CH, CH, 0, xt, CH, (size_t)NPIX * CH,
        vh, NPIX, (size_t)CH * NPIX, bv, CH);
    // scores + fused block softmax -> p, m_block, l_block
    scores2_kernel<<<dim3(NPIX / 128, NPIX / 128, BATCH), 256, S2SMEM>>>();
    // per-row global stats -> scale
    rowstats_kernel<<<BATCH * NPIX / 256, 256>>>();
    // attn = p * scale (in place)
    norm_kernel<<<BATCH * NPIX, 256>>>();
    // out[c][i] = V[c][j] * attn[i][j]^T
    av2_kernel<<<dim3(NPIX / 128, CH / 128, BATCH), 256, AVSMEM>>>(vh, ah, out);
}

// round 12
// speedup vs baseline: 1.0707x; 1.0707x over previous
#include <cuda_runtime.h>
#include <cuda_bf16.h>
#include <cuda_fp16.h>
#include <math.h>
#include <stdint.h>

#define BATCH 8
#define CH    256
#define NPIX  4096
#define NBLK  32            // NPIX / 128 score blocks per row

// Packed split formats: u32 = lo16(hi) | lo16(lo)<<16, value ~= hi + lo
static __device__ uint32_t g_wp[3 * CH * CH];                  // packed bf16 wq|wk|wv
static __device__ uint32_t g_xt[(size_t)BATCH * NPIX * CH];    // x^T  [b][n][c] bf16-split
static __device__ uint32_t g_qt[(size_t)BATCH * NPIX * CH];    // Q^T  [b][n][c] bf16-split
static __device__ uint32_t g_kt[(size_t)BATCH * NPIX * CH];    // K^T  [b][n][c] bf16-split
static __device__ __half   g_vh[(size_t)BATCH * CH * NPIX];    // V    [b][c][n] fp16 single
static __device__ __half   g_ah[(size_t)BATCH * NPIX * NPIX];  // p fp16 [b][i][j]
static __device__ float    g_bm[(size_t)BATCH * NBLK * NPIX];  // block row max [b][jb][i]
static __device__ float    g_bl[(size_t)BATCH * NBLK * NPIX];  // block row sum [b][jb][i]
static __device__ float    g_sc[(size_t)BATCH * NBLK * NPIX];  // scale [b][jb][i]

__device__ __forceinline__ uint32_t smem_u32(const void* p) {
    uint32_t a;
    asm("{ .reg .u64 t; cvta.to.shared.u64 t, %1; cvt.u32.u64 %0, t; }" : "=r"(a) : "l"(p));
    return a;
}
__device__ __forceinline__ uint32_t pack_split(float v) {         // bf16 hi+lo
    __nv_bfloat16 h = __float2bfloat16(v);
    float r = v - __bfloat162float(h);
    __nv_bfloat16 l = __float2bfloat16(r);
    return (uint32_t)__bfloat16_as_ushort(h) | ((uint32_t)__bfloat16_as_ushort(l) << 16);
}
__device__ __forceinline__ void cp16(uint32_t saddr, const void* g) {
    uint64_t ga;
    asm("cvta.to.global.u64 %0, %1;" : "=l"(ga) : "l"(g));
    asm volatile("cp.async.cg.shared.global [%0], [%1], 16;" :: "r"(saddr), "l"(ga));
}
#define CP_COMMIT() asm volatile("cp.async.commit_group;" ::: "memory")
#define CP_WAIT1()  asm volatile("cp.async.wait_group 1;"  ::: "memory")
#define CP_WAIT0()  asm volatile("cp.async.wait_group 0;"  ::: "memory")
#define LDS64(a, b, addr) \
    asm volatile("ld.shared.v2.u32 {%0,%1}, [%2];" : "=r"(a), "=r"(b) : "r"(addr))
#define LDS32(a, addr) \
    asm volatile("ld.shared.u32 %0, [%1];" : "=r"(a) : "r"(addr))
#define LDSF(a, addr) \
    asm volatile("ld.shared.f32 %0, [%1];" : "=f"(a) : "r"(addr))
#define MMAB(d, a, b0, b1)                                                        \
    asm volatile("mma.sync.aligned.m16n8k16.row.col.f32.bf16.bf16.f32 "           \
        "{%0,%1,%2,%3}, {%4,%5,%6,%7}, {%8,%9}, {%0,%1,%2,%3};"                   \
        : "+f"((d)[0]), "+f"((d)[1]), "+f"((d)[2]), "+f"((d)[3])                  \
        : "r"((a)[0]), "r"((a)[1]), "r"((a)[2]), "r"((a)[3]), "r"(b0), "r"(b1))
#define MMAH(d, a, b0, b1)                                                        \
    asm volatile("mma.sync.aligned.m16n8k16.row.col.f32.f16.f16.f32 "             \
        "{%0,%1,%2,%3}, {%4,%5,%6,%7}, {%8,%9}, {%0,%1,%2,%3};"                   \
        : "+f"((d)[0]), "+f"((d)[1]), "+f"((d)[2]), "+f"((d)[3])                  \
        : "r"((a)[0]), "r"((a)[1]), "r"((a)[2]), "r"((a)[3]), "r"(b0), "r"(b1))

// ---------------------------------------------------------------------------
// QKV GEMM (proven): packed split-bf16, 3-MMA. CTA 128x256, 1 CTA/SM.
// MODE: 1 = packed bf16-split out + bias[col]; 2 = fp16 single out + bias[row]
// ---------------------------------------------------------------------------
#define BM 128
#define BN 256
#define BK 32
#define A_U32S  (BM * 40)
#define B_U32S  (BN * 40)
#define A_BYTES (A_U32S * 4)
#define BUF_BYTES ((A_U32S + B_U32S) * 4)   // 61440
#define GEMM_SMEM (3 * BUF_BYTES)           // 184320

__device__ __forceinline__ void load_tiles(const uint32_t* __restrict__ Ag, int lda,
                                           const uint32_t* __restrict__ Bg, int ldb,
                                           uint32_t sbase, int tid) {
    #pragma unroll
    for (int i = 0; i < 4; i++) {
        int t = i * 256 + tid;
        int row = t >> 3, q = t & 7;
        cp16(sbase + (uint32_t)(row * 40 + q * 4) * 4, Ag + (size_t)row * lda + q * 4);
    }
    #pragma unroll
    for (int i = 0; i < 8; i++) {
        int t = i * 256 + tid;
        int row = t >> 3, q = t & 7;
        cp16(sbase + A_BYTES + (uint32_t)(row * 40 + q * 4) * 4, Bg + (size_t)row * ldb + q * 4);
    }
}

__device__ __forceinline__ void compute_tile(uint32_t sa, int lane, int wm, int wn,
                                             float (&acc)[4][8][4]) {
    uint32_t sb = sa + A_BYTES;
    #pragma unroll
    for (int ks = 0; ks < 2; ks++) {
        const int kc = ks * 16 + (lane & 3) * 2;
        uint32_t ah[4][4], al[4][4];
        #pragma unroll
        for (int mt = 0; mt < 4; mt++) {
            int r = wm * 64 + mt * 16 + (lane >> 2);
            uint32_t x0, x1, y0, y1, x2, x3, y2, y3;
            LDS64(x0, x1, sa + (uint32_t)(r * 40 + kc) * 4);
            LDS64(y0, y1, sa + (uint32_t)((r + 8) * 40 + kc) * 4);
            LDS64(x2, x3, sa + (uint32_t)(r * 40 + kc + 8) * 4);
            LDS64(y2, y3, sa + (uint32_t)((r + 8) * 40 + kc + 8) * 4);
            ah[mt][0] = __byte_perm(x0, x1, 0x5410); al[mt][0] = __byte_perm(x0, x1, 0x7632);
            ah[mt][1] = __byte_perm(y0, y1, 0x5410); al[mt][1] = __byte_perm(y0, y1, 0x7632);
            ah[mt][2] = __byte_perm(x2, x3, 0x5410); al[mt][2] = __byte_perm(x2, x3, 0x7632);
            ah[mt][3] = __byte_perm(y2, y3, 0x5410); al[mt][3] = __byte_perm(y2, y3, 0x7632);
        }
        #pragma unroll
        for (int nt = 0; nt < 8; nt++) {
            int r = wn * 64 + nt * 8 + (lane >> 2);
            uint32_t u0, u1, u2, u3;
            LDS64(u0, u1, sb + (uint32_t)(r * 40 + kc) * 4);
            LDS64(u2, u3, sb + (uint32_t)(r * 40 + kc + 8) * 4);
            uint32_t bh0 = __byte_perm(u0, u1, 0x5410), bh1 = __byte_perm(u2, u3, 0x5410);
            uint32_t bl0 = __byte_perm(u0, u1, 0x7632), bl1 = __byte_perm(u2, u3, 0x7632);
            #pragma unroll
            for (int mt = 0; mt < 4; mt++) {
                MMAB(acc[mt][nt], ah[mt], bh0, bh1);
                MMAB(acc[mt][nt], ah[mt], bl0, bl1);
                MMAB(acc[mt][nt], al[mt], bh0, bh1);
            }
        }
    }
}

template<int MODE>
__global__ __launch_bounds__(256)
void gemm_kernel(const uint32_t* __restrict__ A, int lda, size_t sA,
                 const uint32_t* __restrict__ B, int ldb, size_t sB,
                 void* __restrict__ Dv, int ldd, size_t sD,
                 const float* __restrict__ bias, int K)
{
    extern __shared__ __align__(16) uint32_t smraw[];
    const uint32_t smbase = smem_u32(smraw);
    const int tid = threadIdx.x;
    const int lane = tid & 31, wid = tid >> 5;
    const int wm = wid >> 2, wn = wid & 3;
    const int z = blockIdx.z;
    const int bm = blockIdx.y * BM, bn = blockIdx.x * BN;

    A += (size_t)z * sA + (size_t)bm * lda;
    B += (size_t)z * sB + (size_t)bn * ldb;

    float acc[4][8][4];
    #pragma unroll
    for (int i = 0; i < 4; i++)
        #pragma unroll
        for (int j = 0; j < 8; j++)
            #pragma unroll
            for (int v = 0; v < 4; v++) acc[i][j][v] = 0.f;

    const int S = K / BK;
    load_tiles(A, lda, B, ldb, smbase, tid);
    CP_COMMIT();
    load_tiles(A + BK, lda, B + BK, ldb, smbase + BUF_BYTES, tid);
    CP_COMMIT();

    #pragma unroll 1
    for (int s = 0; s < S; s++) {
        CP_WAIT1();
        __syncthreads();
        if (s + 2 < S)
            load_tiles(A + (s + 2) * BK, lda, B + (s + 2) * BK, ldb,
                       smbase + (uint32_t)((s + 2) % 3) * BUF_BYTES, tid);
        CP_COMMIT();
        compute_tile(smbase + (uint32_t)(s % 3) * BUF_BYTES, lane, wm, wn, acc);
    }

    #pragma unroll
    for (int nt = 0; nt < 8; nt++) {
        int col = bn + wn * 64 + nt * 8 + (lane & 3) * 2;
        float bc0 = 0.f, bc1 = 0.f;
        if (MODE == 1) { bc0 = bias[col]; bc1 = bias[col + 1]; }
        #pragma unroll
        for (int mt = 0; mt < 4; mt++) {
            int r0 = bm + wm * 64 + mt * 16 + (lane >> 2);
            if (MODE == 1) {
                uint32_t* D = (uint32_t*)Dv + (size_t)z * sD;
                uint32_t p0 = pack_split(acc[mt][nt][0] + bc0);
                uint32_t p1 = pack_split(acc[mt][nt][1] + bc1);
                uint32_t p2 = pack_split(acc[mt][nt][2] + bc0);
                uint32_t p3 = pack_split(acc[mt][nt][3] + bc1);
                *(uint2*)&D[(size_t)r0 * ldd + col] = make_uint2(p0, p1);
                *(uint2*)&D[(size_t)(r0 + 8) * ldd + col] = make_uint2(p2, p3);
            } else {
                __half* D = (__half*)Dv + (size_t)z * sD;
                float b0 = bias[r0], b8 = bias[r0 + 8];
                __half2 v01 = __floats2half2_rn(acc[mt][nt][0] + b0, acc[mt][nt][1] + b0);
                __half2 v23 = __floats2half2_rn(acc[mt][nt][2] + b8, acc[mt][nt][3] + b8);
                *(__half2*)&D[(size_t)r0 * ldd + col] = v01;
                *(__half2*)&D[(size_t)(r0 + 8) * ldd + col] = v23;
            }
        }
    }
}

// ---------------------------------------------------------------------------
// Scores GEMM with fused block-softmax epilogue (R11). 2 CTAs/SM, CTA 128x128.
// Emits p = exp(s - m_block) fp16, plus m_block/l_block.
// ---------------------------------------------------------------------------
#define S2TILE 20480
#define S2BUF  (2 * S2TILE)
#define S2RED  (2 * S2BUF)
#define S2SMEM (S2RED + 4096)

__device__ __forceinline__ void load_s2(const uint32_t* __restrict__ Ag,
                                        const uint32_t* __restrict__ Bg,
                                        uint32_t sbase, int tid) {
    #pragma unroll
    for (int i = 0; i < 4; i++) {
        int t = i * 256 + tid;
        int row = t >> 3, q = t & 7;
        cp16(sbase + (uint32_t)(row * 40 + q * 4) * 4, Ag + (size_t)row * CH + q * 4);
    }
    #pragma unroll
    for (int i = 0; i < 4; i++) {
        int t = i * 256 + tid;
        int row = t >> 3, q = t & 7;
        cp16(sbase + S2TILE + (uint32_t)(row * 40 + q * 4) * 4, Bg + (size_t)row * CH + q * 4);
    }
}

__global__ __launch_bounds__(256, 2)
void scores2_kernel()
{
    extern __shared__ __align__(16) uint32_t smraw[];
    const uint32_t smbase = smem_u32(smraw);
    const int tid = threadIdx.x;
    const int lane = tid & 31, wid = tid >> 5;
    const int wm = wid >> 2, wn = wid & 3;
    const int z = blockIdx.z;
    const int bm = blockIdx.y * 128, bn = blockIdx.x * 128;
    const int jb = blockIdx.x;

    const uint32_t* A = g_qt + (size_t)z * NPIX * CH + (size_t)bm * CH;
    const uint32_t* B = g_kt + (size_t)z * NPIX * CH + (size_t)bn * CH;

    float acc[4][4][4];
    #pragma unroll
    for (int i = 0; i < 4; i++)
        #pragma unroll
        for (int j = 0; j < 4; j++)
            #pragma unroll
            for (int v = 0; v < 4; v++) acc[i][j][v] = 0.f;

    const int qrow = lane >> 2, qcol = lane & 3;
    const int S = CH / BK;   // 8

    load_s2(A, B, smbase, tid);
    CP_COMMIT();

    #pragma unroll 1
    for (int s = 0; s < S; s++) {
        __syncthreads();
        if (s + 1 < S) {
            load_s2(A + (s + 1) * BK, B + (s + 1) * BK,
                    smbase + (uint32_t)((s + 1) & 1) * S2BUF, tid);
            CP_COMMIT();
            CP_WAIT1();
        } else {
            CP_WAIT0();
        }
        __syncthreads();
        uint32_t sa = smbase + (uint32_t)(s & 1) * S2BUF;
        uint32_t sb = sa + S2TILE;
        #pragma unroll
        for (int ks = 0; ks < 2; ks++) {
            const int kc = ks * 16 + qcol * 2;
            uint32_t ah[4][4], al[4][4];
            #pragma unroll
            for (int mt = 0; mt < 4; mt++) {
                int r = wm * 64 + mt * 16 + qrow;
                uint32_t x0, x1, y0, y1, x2, x3, y2, y3;
                LDS64(x0, x1, sa + (uint32_t)(r * 40 + kc) * 4);
                LDS64(y0, y1, sa + (uint32_t)((r + 8) * 40 + kc) * 4);
                LDS64(x2, x3, sa + (uint32_t)(r * 40 + kc + 8) * 4);
                LDS64(y2, y3, sa + (uint32_t)((r + 8) * 40 + kc + 8) * 4);
                ah[mt][0] = __byte_perm(x0, x1, 0x5410); al[mt][0] = __byte_perm(x0, x1, 0x7632);
                ah[mt][1] = __byte_perm(y0, y1, 0x5410); al[mt][1] = __byte_perm(y0, y1, 0x7632);
                ah[mt][2] = __byte_perm(x2, x3, 0x5410); al[mt][2] = __byte_perm(x2, x3, 0x7632);
                ah[mt][3] = __byte_perm(y2, y3, 0x5410); al[mt][3] = __byte_perm(y2, y3, 0x7632);
            }
            #pragma unroll
            for (int nt = 0; nt < 4; nt++) {
                int r = wn * 32 + nt * 8 + qrow;
                uint32_t u0, u1, u2, u3;
                LDS64(u0, u1, sb + (uint32_t)(r * 40 + kc) * 4);
                LDS64(u2, u3, sb + (uint32_t)(r * 40 + kc + 8) * 4);
                uint32_t bh0 = __byte_perm(u0, u1, 0x5410), bh1 = __byte_perm(u2, u3, 0x5410);
                uint32_t bl0 = __byte_perm(u0, u1, 0x7632), bl1 = __byte_perm(u2, u3, 0x7632);
                #pragma unroll
                for (int mt = 0; mt < 4; mt++) {
                    MMAB(acc[mt][nt], ah[mt], bh0, bh1);
                    MMAB(acc[mt][nt], ah[mt], bl0, bl1);
                    MMAB(acc[mt][nt], al[mt], bh0, bh1);
                }
            }
        }
    }

    // ---- fused block-softmax epilogue ----
    float* redm = (float*)smraw + (S2RED >> 2);
    float* redl = redm + 512;

    float mrow[4][2];
    #pragma unroll
    for (int mt = 0; mt < 4; mt++)
        #pragma unroll
        for (int h = 0; h < 2; h++) {
            float v = -1e30f;
            #pragma unroll
            for (int nt = 0; nt < 4; nt++)
                v = fmaxf(v, fmaxf(acc[mt][nt][h * 2], acc[mt][nt][h * 2 + 1]));
            v = fmaxf(v, __shfl_xor_sync(0xffffffffu, v, 1));
            v = fmaxf(v, __shfl_xor_sync(0xffffffffu, v, 2));
            mrow[mt][h] = v;
            if (qcol == 0)
                redm[wn * 128 + wm * 64 + mt * 16 + qrow + h * 8] = v;
        }
    __syncthreads();
    #pragma unroll
    for (int mt = 0; mt < 4; mt++)
        #pragma unroll
        for (int h = 0; h < 2; h++) {
            int lr = wm * 64 + mt * 16 + qrow + h * 8;
            mrow[mt][h] = fmaxf(fmaxf(redm[lr], redm[128 + lr]),
                                fmaxf(redm[256 + lr], redm[384 + lr]));
        }

    __half* Pb = g_ah + (size_t)z * NPIX * NPIX;
    float ls[4][2] = {{0.f,0.f},{0.f,0.f},{0.f,0.f},{0.f,0.f}};
    #pragma unroll
    for (int nt = 0; nt < 4; nt++) {
        int colg = bn + wn * 32 + nt * 8 + qcol * 2;
        #pragma unroll
        for (int mt = 0; mt < 4; mt++) {
            int r0 = bm + wm * 64 + mt * 16 + qrow;
            float p0 = __expf(acc[mt][nt][0] - mrow[mt][0]);
            float p1 = __expf(acc[mt][nt][1] - mrow[mt][0]);
            float p2 = __expf(acc[mt][nt][2] - mrow[mt][1]);
            float p3 = __expf(acc[mt][nt][3] - mrow[mt][1]);
            ls[mt][0] += p0 + p1;
            ls[mt][1] += p2 + p3;
            *(__half2*)&Pb[(size_t)r0 * NPIX + colg]       = __floats2half2_rn(p0, p1);
            *(__half2*)&Pb[(size_t)(r0 + 8) * NPIX + colg] = __floats2half2_rn(p2, p3);
        }
    }
    #pragma unroll
    for (int mt = 0; mt < 4; mt++)
        #pragma unroll
        for (int h = 0; h < 2; h++) {
            float v = ls[mt][h];
            v += __shfl_xor_sync(0xffffffffu, v, 1);
            v += __shfl_xor_sync(0xffffffffu, v, 2);
            if (qcol == 0)
                redl[wn * 128 + wm * 64 + mt * 16 + qrow + h * 8] = v;
        }
    __syncthreads();
    if (wn == 0 && qcol == 0) {
        float* BM_ = g_bm + ((size_t)z * NBLK + jb) * NPIX + bm;
        float* BL_ = g_bl + ((size_t)z * NBLK + jb) * NPIX + bm;
        #pragma unroll
        for (int mt = 0; mt < 4; mt++)
            #pragma unroll
            for (int h = 0; h < 2; h++) {
                int lr = wm * 64 + mt * 16 + qrow + h * 8;
                BM_[lr] = mrow[mt][h];
                BL_[lr] = redl[lr] + redl[128 + lr] + redl[256 + lr] + redl[384 + lr];
            }
    }
}

// ---------------------------------------------------------------------------
// Row stats: scale[z][jb][i] = exp(m_b - m_g) / tot
// ---------------------------------------------------------------------------
__global__ __launch_bounds__(256) void rowstats_kernel()
{
    int t = blockIdx.x * 256 + threadIdx.x;
    int z = t >> 12, i = t & (NPIX - 1);
    size_t base = (size_t)z * NBLK * NPIX + i;

    float mv[NBLK];
    float mg = -1e30f;
    #pragma unroll
    for (int jb = 0; jb < NBLK; jb++) {
        mv[jb] = g_bm[base + (size_t)jb * NPIX];
        mg = fmaxf(mg, mv[jb]);
    }
    float tot = 0.f;
    #pragma unroll
    for (int jb = 0; jb < NBLK; jb++)
        tot += g_bl[base + (size_t)jb * NPIX] * __expf(mv[jb] - mg);
    float inv = 1.0f / tot;
    #pragma unroll
    for (int jb = 0; jb < NBLK; jb++)
        g_sc[base + (size_t)jb * NPIX] = __expf(mv[jb] - mg) * inv;
}

// ---------------------------------------------------------------------------
// AV GEMM with in-loop normalization: out[c][i] = sum_j V[c][j] * p[i][j] *
// scale[jb(i,j)][i]. 2 CTAs/SM, CTA 128(c)x128(i). Scale table staged in smem;
// B fragments multiplied by per-row half2 scale (constant within a jb block).
// ---------------------------------------------------------------------------
#define AVTILE 10240
#define AVBUF  (2 * AVTILE)
#define AVSC   (3 * AVBUF)                  // 61440: scale table offset
#define AVSMEM (AVSC + NBLK * 128 * 4)      // + 16384 = 77824

__device__ __forceinline__ void load_av2(const __half* __restrict__ Ag,
                                         const __half* __restrict__ Bg,
                                         uint32_t sbase, int tid) {
    #pragma unroll
    for (int i = 0; i < 2; i++) {
        int t = i * 256 + tid;
        int row = t >> 2, q = t & 3;
        cp16(sbase + (uint32_t)(row * 80 + q * 16), Ag + (size_t)row * NPIX + q * 8);
    }
    #pragma unroll
    for (int i = 0; i < 2; i++) {
        int t = i * 256 + tid;
        int row = t >> 2, q = t & 3;
        cp16(sbase + AVTILE + (uint32_t)(row * 80 + q * 16), Bg + (size_t)row * NPIX + q * 8);
    }
}

__global__ __launch_bounds__(256, 2)
void av3_kernel(const __half* __restrict__ A,   // g_vh
                const __half* __restrict__ B,    // g_ah (p)
                float* __restrict__ D)           // out
{
    extern __shared__ __align__(16) uint32_t smraw[];
    const uint32_t smbase = smem_u32(smraw);
    const int tid = threadIdx.x;
    const int lane = tid & 31, wid = tid >> 5;
    const int wm = wid >> 2, wn = wid & 3;
    const int z = blockIdx.z;
    const int bm = blockIdx.y * 128, bn = blockIdx.x * 128;

    A += (size_t)z * CH * NPIX + (size_t)bm * NPIX;
    B += (size_t)z * NPIX * NPIX + (size_t)bn * NPIX;
    D += (size_t)z * CH * NPIX;

    // Stage scale table: [jb 0..31][i 0..127] for i in [bn, bn+128)
    {
        const float* SC = g_sc + (size_t)z * NBLK * NPIX + bn;
        float* sdst = (float*)smraw + (AVSC >> 2);
        #pragma unroll
        for (int t = 0; t < 16; t++) {
            int task = t * 256 + tid;          // 0..4095
            int jbb = task >> 7, ii = task & 127;
            sdst[jbb * 128 + ii] = SC[(size_t)jbb * NPIX + ii];
        }
    }

    float acc[4][4][4];
    #pragma unroll
    for (int i = 0; i < 4; i++)
        #pragma unroll
        for (int j = 0; j < 4; j++)
            #pragma unroll
            for (int v = 0; v < 4; v++) acc[i][j][v] = 0.f;

    const int qrow = lane >> 2, qcol = lane & 3;
    const int S = NPIX / BK;   // 128

    load_av2(A, B, smbase, tid);
    CP_COMMIT();
    load_av2(A + BK, B + BK, smbase + AVBUF, tid);
    CP_COMMIT();

    uint32_t sreg[4];          // half2 scale per nt row, current jb

    #pragma unroll 1
    for (int s = 0; s < S; s++) {
        CP_WAIT1();
        __syncthreads();
        if (s + 2 < S)
            load_av2(A + (s + 2) * BK, B + (s + 2) * BK,
                     smbase + (uint32_t)((s + 2) % 3) * AVBUF, tid);
        CP_COMMIT();

        if ((s & 3) == 0) {
            int jbb = s >> 2;
            #pragma unroll
            for (int nt = 0; nt < 4; nt++) {
                int cr = wn * 32 + nt * 8 + qrow;
                float sv;
                LDSF(sv, smbase + AVSC + (uint32_t)(jbb * 128 + cr) * 4);
                __half2 h2 = __float2half2_rn(sv);
                sreg[nt] = *(uint32_t*)&h2;
            }
        }

        uint32_t sa = smbase + (uint32_t)(s % 3) * AVBUF;
        uint32_t sb = sa + AVTILE;
        #pragma unroll
        for (int ks = 0; ks < 2; ks++) {
            const int kc = ks * 16 + qcol * 2;
            uint32_t af[4][4];
            #pragma unroll
            for (int mt = 0; mt < 4; mt++) {
                int r = wm * 64 + mt * 16 + qrow;
                LDS32(af[mt][0], sa + (uint32_t)(r * 80 + kc * 2));
                LDS32(af[mt][1], sa + (uint32_t)((r + 8) * 80 + kc * 2));
                LDS32(af[mt][2], sa + (uint32_t)(r * 80 + (kc + 8) * 2));
                LDS32(af[mt][3], sa + (uint32_t)((r + 8) * 80 + (kc + 8) * 2));
            }
            #pragma unroll
            for (int nt = 0; nt < 4; nt++) {
                int cr = wn * 32 + nt * 8 + qrow;
                uint32_t b0, b1;
                LDS32(b0, sb + (uint32_t)(cr * 80 + kc * 2));
                LDS32(b1, sb + (uint32_t)(cr * 80 + (kc + 8) * 2));
                __half2 hb0 = __hmul2(*(__half2*)&b0, *(__half2*)&sreg[nt]);
                __half2 hb1 = __hmul2(*(__half2*)&b1, *(__half2*)&sreg[nt]);
                b0 = *(uint32_t*)&hb0;
                b1 = *(uint32_t*)&hb1;
                #pragma unroll
                for (int mt = 0; mt < 4; mt++)
                    MMAH(acc[mt][nt], af[mt], b0, b1);
            }
        }
    }

    #pragma unroll
    for (int nt = 0; nt < 4; nt++) {
        int col = bn + wn * 32 + nt * 8 + qcol * 2;
        #pragma unroll
        for (int mt = 0; mt < 4; mt++) {
            int r0 = bm + wm * 64 + mt * 16 + qrow;
            *(float2*)&D[(size_t)r0 * NPIX + col] =
                make_float2(acc[mt][nt][0], acc[mt][nt][1]);
            *(float2*)&D[(size_t)(r0 + 8) * NPIX + col] =
                make_float2(acc[mt][nt][2], acc[mt][nt][3]);
        }
    }
}

// ---------------------------------------------------------------------------
// Packing kernels
// ---------------------------------------------------------------------------
__global__ __launch_bounds__(256) void pack_w_kernel(
    const float* __restrict__ wq, const float* __restrict__ wk,
    const float* __restrict__ wv)
{
    int i = blockIdx.x * 256 + threadIdx.x;
    g_wp[i]               = pack_split(wq[i]);
    g_wp[CH * CH + i]     = pack_split(wk[i]);
    g_wp[2 * CH * CH + i] = pack_split(wv[i]);
}

__global__ __launch_bounds__(256) void pack_xt_kernel(const float* __restrict__ x)
{
    __shared__ float t[32][33];
    const int b = blockIdx.z;
    const int n0 = blockIdx.x * 32, c0 = blockIdx.y * 32;
    const int tx = threadIdx.x, ty = threadIdx.y;   // 32 x 8
    const float* xb = x + (size_t)b * CH * NPIX;
    #pragma unroll
    for (int i = 0; i < 4; i++)
        t[ty * 4 + i][tx] = xb[(size_t)(c0 + ty * 4 + i) * NPIX + n0 + tx];
    __syncthreads();
    uint32_t* xt = g_xt + (size_t)b * NPIX * CH;
    #pragma unroll
    for (int i = 0; i < 4; i++)
        xt[(size_t)(n0 + ty * 4 + i) * CH + c0 + tx] = pack_split(t[tx][ty * 4 + i]);
}

// ---------------------------------------------------------------------------
extern "C" void kernel_launch(void* const* d_in, const int* in_sizes, int n_in,
                              void* d_out, int out_size)
{
    const float* x  = (const float*)d_in[0];
    const float* wq = (const float*)d_in[1];
    const float* bq = (const float*)d_in[2];
    const float* wk = (const float*)d_in[3];
    const float* bk = (const float*)d_in[4];
    const float* wv = (const float*)d_in[5];
    const float* bv = (const float*)d_in[6];
    float* out = (float*)d_out;

    void *pwp, *pxt, *pqt, *pkt, *pvh, *pah;
    cudaGetSymbolAddress(&pwp, g_wp);
    cudaGetSymbolAddress(&pxt, g_xt);
    cudaGetSymbolAddress(&pqt, g_qt);
    cudaGetSymbolAddress(&pkt, g_kt);
    cudaGetSymbolAddress(&pvh, g_vh);
    cudaGetSymbolAddress(&pah, g_ah);
    uint32_t* wp = (uint32_t*)pwp;
    uint32_t* xt = (uint32_t*)pxt;
    uint32_t* qt = (uint32_t*)pqt;
    uint32_t* kt = (uint32_t*)pkt;
    __half*   vh = (__half*)pvh;
    __half*   ah = (__half*)pah;

    cudaFuncSetAttribute(gemm_kernel<1>, cudaFuncAttributeMaxDynamicSharedMemorySize, GEMM_SMEM);
    cudaFuncSetAttribute(gemm_kernel<2>, cudaFuncAttributeMaxDynamicSharedMemorySize, GEMM_SMEM);
    cudaFuncSetAttribute(scores2_kernel, cudaFuncAttributeMaxDynamicSharedMemorySize, S2SMEM);
    cudaFuncSetAttribute(av3_kernel,     cudaFuncAttributeMaxDynamicSharedMemorySize, AVSMEM);

    pack_w_kernel<<<CH * CH / 256, 256>>>(wq, wk, wv);
    pack_xt_kernel<<<dim3(NPIX / 32, CH / 32, BATCH), dim3(32, 8)>>>(x);

    // Q^T[n][c] = X^T[n][k] * Wq[c][k]^T + bq
    gemm_kernel<1><<<dim3(1, 32, BATCH), 256, GEMM_SMEM>>>(
        xt, CH, (size_t)NPIX * CH, wp, CH, 0,
        qt, CH, (size_t)NPIX * CH, bq, CH);
    gemm_kernel<1><<<dim3(1, 32, BATCH), 256, GEMM_SMEM>>>(
        xt, CH, (size_t)NPIX * CH, wp + CH * CH, CH, 0,
        kt, CH, (size_t)NPIX * CH, bk, CH);
    // V[c][n] fp16 single plane
    gemm_kernel<2><<<dim3(NPIX / BN, CH / BM, BATCH), 256, GEMM_SMEM>>>(
        wp + 2 * CH * CH, CH, 0, xt, CH, (size_t)NPIX * CH,
        vh, NPIX, (size_t)CH * NPIX, bv, CH);
    // scores + fused block softmax -> p, m_block, l_block
    scores2_kernel<<<dim3(NPIX / 128, NPIX / 128, BATCH), 256, S2SMEM>>>();
    // per-row global stats -> scale
    rowstats_kernel<<<BATCH * NPIX / 256, 256>>>();
    // out[c][i] = sum_j V[c][j] * p[i][j] * scale  (norm fused into AV)
    av3_kernel<<<dim3(NPIX / 128, CH / 128, BATCH), 256, AVSMEM>>>(vh, ah, out);
}

// round 13
// speedup vs baseline: 1.0984x; 1.0258x over previous
#include <cuda_runtime.h>
#include <cuda_bf16.h>
#include <cuda_fp16.h>
#include <math.h>
#include <stdint.h>

#define BATCH 8
#define CH    256
#define NPIX  4096
#define NBLK  32            // NPIX / 128 score blocks per row
#define BK    32

// Packed split formats: u32 = lo16(hi) | lo16(lo)<<16, value ~= hi + lo
static __device__ uint32_t g_wp[3 * CH * CH];                  // packed bf16 wq|wk|wv
static __device__ uint32_t g_xt[(size_t)BATCH * NPIX * CH];    // x^T  [b][n][c] bf16-split
static __device__ uint32_t g_qt[(size_t)BATCH * NPIX * CH];    // Q^T  [b][n][c] bf16-split
static __device__ uint32_t g_kt[(size_t)BATCH * NPIX * CH];    // K^T  [b][n][c] bf16-split
static __device__ __half   g_vh[(size_t)BATCH * CH * NPIX];    // V    [b][c][n] fp16 single
static __device__ __half   g_ah[(size_t)BATCH * NPIX * NPIX];  // p fp16 [b][i][j]
static __device__ float    g_bm[(size_t)BATCH * NBLK * NPIX];  // block row max
static __device__ float    g_bl[(size_t)BATCH * NBLK * NPIX];  // block row sum
static __device__ float    g_sc[(size_t)BATCH * NBLK * NPIX];  // scale

__device__ __forceinline__ uint32_t smem_u32(const void* p) {
    uint32_t a;
    asm("{ .reg .u64 t; cvta.to.shared.u64 t, %1; cvt.u32.u64 %0, t; }" : "=r"(a) : "l"(p));
    return a;
}
__device__ __forceinline__ uint32_t pack_split(float v) {
    __nv_bfloat16 h = __float2bfloat16(v);
    float r = v - __bfloat162float(h);
    __nv_bfloat16 l = __float2bfloat16(r);
    return (uint32_t)__bfloat16_as_ushort(h) | ((uint32_t)__bfloat16_as_ushort(l) << 16);
}
__device__ __forceinline__ void cp16(uint32_t saddr, const void* g) {
    uint64_t ga;
    asm("cvta.to.global.u64 %0, %1;" : "=l"(ga) : "l"(g));
    asm volatile("cp.async.cg.shared.global [%0], [%1], 16;" :: "r"(saddr), "l"(ga));
}
#define CP_COMMIT() asm volatile("cp.async.commit_group;" ::: "memory")
#define CP_WAIT1()  asm volatile("cp.async.wait_group 1;"  ::: "memory")
#define CP_WAIT0()  asm volatile("cp.async.wait_group 0;"  ::: "memory")
#define LDS64(a, b, addr) \
    asm volatile("ld.shared.v2.u32 {%0,%1}, [%2];" : "=r"(a), "=r"(b) : "r"(addr))
#define LDS32(a, addr) \
    asm volatile("ld.shared.u32 %0, [%1];" : "=r"(a) : "r"(addr))
#define LDSF(a, addr) \
    asm volatile("ld.shared.f32 %0, [%1];" : "=f"(a) : "r"(addr))
#define MMAB(d, a, b0, b1)                                                        \
    asm volatile("mma.sync.aligned.m16n8k16.row.col.f32.bf16.bf16.f32 "           \
        "{%0,%1,%2,%3}, {%4,%5,%6,%7}, {%8,%9}, {%0,%1,%2,%3};"                   \
        : "+f"((d)[0]), "+f"((d)[1]), "+f"((d)[2]), "+f"((d)[3])                  \
        : "r"((a)[0]), "r"((a)[1]), "r"((a)[2]), "r"((a)[3]), "r"(b0), "r"(b1))
#define MMAH(d, a, b0, b1)                                                        \
    asm volatile("mma.sync.aligned.m16n8k16.row.col.f32.f16.f16.f32 "             \
        "{%0,%1,%2,%3}, {%4,%5,%6,%7}, {%8,%9}, {%0,%1,%2,%3};"                   \
        : "+f"((d)[0]), "+f"((d)[1]), "+f"((d)[2]), "+f"((d)[3])                  \
        : "r"((a)[0]), "r"((a)[1]), "r"((a)[2]), "r"((a)[3]), "r"(b0), "r"(b1))

// ---------------------------------------------------------------------------
// Shared 128x128 2-CTA/SM GEMM machinery (scores2-proven).
// Warp tile 64(m) x 32(n). 2-stage cp.async, BK=32, K-major packed u32.
// ---------------------------------------------------------------------------
#define S2TILE 20480                        // 128 rows * 40 u32 * 4B
#define S2BUF  (2 * S2TILE)                 // 40960
#define S2RED  (2 * S2BUF)                  // red arrays offset
#define S2SMEM (S2RED + 4096)

__device__ __forceinline__ void load128(const uint32_t* __restrict__ Ag, int lda,
                                        const uint32_t* __restrict__ Bg, int ldb,
                                        uint32_t sbase, int tid) {
    #pragma unroll
    for (int i = 0; i < 4; i++) {
        int t = i * 256 + tid;
        int row = t >> 3, q = t & 7;
        cp16(sbase + (uint32_t)(row * 40 + q * 4) * 4, Ag + (size_t)row * lda + q * 4);
    }
    #pragma unroll
    for (int i = 0; i < 4; i++) {
        int t = i * 256 + tid;
        int row = t >> 3, q = t & 7;
        cp16(sbase + S2TILE + (uint32_t)(row * 40 + q * 4) * 4, Bg + (size_t)row * ldb + q * 4);
    }
}

// Full pipelined mainloop filling acc[4][4][4] (3-pass split-bf16)
__device__ __forceinline__ void gemm128_loop(const uint32_t* __restrict__ A, int lda,
                                             const uint32_t* __restrict__ B, int ldb,
                                             uint32_t smbase, int tid,
                                             int qrow, int qcol, int wm, int wn,
                                             int S, float (&acc)[4][4][4])
{
    load128(A, lda, B, ldb, smbase, tid);
    CP_COMMIT();

    #pragma unroll 1
    for (int s = 0; s < S; s++) {
        __syncthreads();
        if (s + 1 < S) {
            load128(A + (s + 1) * BK, lda, B + (s + 1) * BK, ldb,
                    smbase + (uint32_t)((s + 1) & 1) * S2BUF, tid);
            CP_COMMIT();
            CP_WAIT1();
        } else {
            CP_WAIT0();
        }
        __syncthreads();
        uint32_t sa = smbase + (uint32_t)(s & 1) * S2BUF;
        uint32_t sb = sa + S2TILE;
        #pragma unroll
        for (int ks = 0; ks < 2; ks++) {
            const int kc = ks * 16 + qcol * 2;
            uint32_t ah[4][4], al[4][4];
            #pragma unroll
            for (int mt = 0; mt < 4; mt++) {
                int r = wm * 64 + mt * 16 + qrow;
                uint32_t x0, x1, y0, y1, x2, x3, y2, y3;
                LDS64(x0, x1, sa + (uint32_t)(r * 40 + kc) * 4);
                LDS64(y0, y1, sa + (uint32_t)((r + 8) * 40 + kc) * 4);
                LDS64(x2, x3, sa + (uint32_t)(r * 40 + kc + 8) * 4);
                LDS64(y2, y3, sa + (uint32_t)((r + 8) * 40 + kc + 8) * 4);
                ah[mt][0] = __byte_perm(x0, x1, 0x5410); al[mt][0] = __byte_perm(x0, x1, 0x7632);
                ah[mt][1] = __byte_perm(y0, y1, 0x5410); al[mt][1] = __byte_perm(y0, y1, 0x7632);
                ah[mt][2] = __byte_perm(x2, x3, 0x5410); al[mt][2] = __byte_perm(x2, x3, 0x7632);
                ah[mt][3] = __byte_perm(y2, y3, 0x5410); al[mt][3] = __byte_perm(y2, y3, 0x7632);
            }
            #pragma unroll
            for (int nt = 0; nt < 4; nt++) {
                int r = wn * 32 + nt * 8 + qrow;
                uint32_t u0, u1, u2, u3;
                LDS64(u0, u1, sb + (uint32_t)(r * 40 + kc) * 4);
                LDS64(u2, u3, sb + (uint32_t)(r * 40 + kc + 8) * 4);
                uint32_t bh0 = __byte_perm(u0, u1, 0x5410), bh1 = __byte_perm(u2, u3, 0x5410);
                uint32_t bl0 = __byte_perm(u0, u1, 0x7632), bl1 = __byte_perm(u2, u3, 0x7632);
                #pragma unroll
                for (int mt = 0; mt < 4; mt++) {
                    MMAB(acc[mt][nt], ah[mt], bh0, bh1);
                    MMAB(acc[mt][nt], ah[mt], bl0, bl1);
                    MMAB(acc[mt][nt], al[mt], bh0, bh1);
                }
            }
        }
    }
}

// ---------------------------------------------------------------------------
// Q/K projections merged: z = b*2 + which. D[n][c] packed bf16-split + bias[c].
// ---------------------------------------------------------------------------
__global__ __launch_bounds__(256, 2)
void qk2_kernel(const float* __restrict__ bq, const float* __restrict__ bk)
{
    extern __shared__ __align__(16) uint32_t smraw[];
    const uint32_t smbase = smem_u32(smraw);
    const int tid = threadIdx.x;
    const int lane = tid & 31, wid = tid >> 5;
    const int wm = wid >> 2, wn = wid & 3;
    const int z = blockIdx.z;
    const int b = z >> 1, which = z & 1;
    const int bm = blockIdx.y * 128, bn = blockIdx.x * 128;
    const int qrow = lane >> 2, qcol = lane & 3;

    const uint32_t* A = g_xt + (size_t)b * NPIX * CH + (size_t)bm * CH;
    const uint32_t* B = g_wp + (size_t)which * CH * CH + (size_t)bn * CH;
    uint32_t* Dst = (which ? g_kt : g_qt) + (size_t)b * NPIX * CH;
    const float* bias = which ? bk : bq;

    float acc[4][4][4];
    #pragma unroll
    for (int i = 0; i < 4; i++)
        #pragma unroll
        for (int j = 0; j < 4; j++)
            #pragma unroll
            for (int v = 0; v < 4; v++) acc[i][j][v] = 0.f;

    gemm128_loop(A, CH, B, CH, smbase, tid, qrow, qcol, wm, wn, CH / BK, acc);

    #pragma unroll
    for (int nt = 0; nt < 4; nt++) {
        int col = bn + wn * 32 + nt * 8 + qcol * 2;
        float bc0 = bias[col], bc1 = bias[col + 1];
        #pragma unroll
        for (int mt = 0; mt < 4; mt++) {
            int r0 = bm + wm * 64 + mt * 16 + qrow;
            uint32_t p0 = pack_split(acc[mt][nt][0] + bc0);
            uint32_t p1 = pack_split(acc[mt][nt][1] + bc1);
            uint32_t p2 = pack_split(acc[mt][nt][2] + bc0);
            uint32_t p3 = pack_split(acc[mt][nt][3] + bc1);
            *(uint2*)&Dst[(size_t)r0 * CH + col] = make_uint2(p0, p1);
            *(uint2*)&Dst[(size_t)(r0 + 8) * CH + col] = make_uint2(p2, p3);
        }
    }
}

// ---------------------------------------------------------------------------
// V projection: D[c][n] fp16 single + bias[c] (row bias).
// A = wv (M = c-out), B = xt (N = n pixels).
// ---------------------------------------------------------------------------
__global__ __launch_bounds__(256, 2)
void v2_kernel(const float* __restrict__ bv)
{
    extern __shared__ __align__(16) uint32_t smraw[];
    const uint32_t smbase = smem_u32(smraw);
    const int tid = threadIdx.x;
    const int lane = tid & 31, wid = tid >> 5;
    const int wm = wid >> 2, wn = wid & 3;
    const int b = blockIdx.z;
    const int bm = blockIdx.y * 128, bn = blockIdx.x * 128;
    const int qrow = lane >> 2, qcol = lane & 3;

    const uint32_t* A = g_wp + (size_t)2 * CH * CH + (size_t)bm * CH;
    const uint32_t* B = g_xt + (size_t)b * NPIX * CH + (size_t)bn * CH;
    __half* Dst = g_vh + (size_t)b * CH * NPIX;

    float acc[4][4][4];
    #pragma unroll
    for (int i = 0; i < 4; i++)
        #pragma unroll
        for (int j = 0; j < 4; j++)
            #pragma unroll
            for (int v = 0; v < 4; v++) acc[i][j][v] = 0.f;

    gemm128_loop(A, CH, B, CH, smbase, tid, qrow, qcol, wm, wn, CH / BK, acc);

    #pragma unroll
    for (int nt = 0; nt < 4; nt++) {
        int col = bn + wn * 32 + nt * 8 + qcol * 2;
        #pragma unroll
        for (int mt = 0; mt < 4; mt++) {
            int r0 = bm + wm * 64 + mt * 16 + qrow;
            float b0 = bv[r0], b8 = bv[r0 + 8];
            __half2 v01 = __floats2half2_rn(acc[mt][nt][0] + b0, acc[mt][nt][1] + b0);
            __half2 v23 = __floats2half2_rn(acc[mt][nt][2] + b8, acc[mt][nt][3] + b8);
            *(__half2*)&Dst[(size_t)r0 * NPIX + col] = v01;
            *(__half2*)&Dst[(size_t)(r0 + 8) * NPIX + col] = v23;
        }
    }
}

// ---------------------------------------------------------------------------
// Scores GEMM with fused block-softmax epilogue (R11/R12-proven).
// ---------------------------------------------------------------------------
__global__ __launch_bounds__(256, 2)
void scores2_kernel()
{
    extern __shared__ __align__(16) uint32_t smraw[];
    const uint32_t smbase = smem_u32(smraw);
    const int tid = threadIdx.x;
    const int lane = tid & 31, wid = tid >> 5;
    const int wm = wid >> 2, wn = wid & 3;
    const int z = blockIdx.z;
    const int bm = blockIdx.y * 128, bn = blockIdx.x * 128;
    const int jb = blockIdx.x;
    const int qrow = lane >> 2, qcol = lane & 3;

    const uint32_t* A = g_qt + (size_t)z * NPIX * CH + (size_t)bm * CH;
    const uint32_t* B = g_kt + (size_t)z * NPIX * CH + (size_t)bn * CH;

    float acc[4][4][4];
    #pragma unroll
    for (int i = 0; i < 4; i++)
        #pragma unroll
        for (int j = 0; j < 4; j++)
            #pragma unroll
            for (int v = 0; v < 4; v++) acc[i][j][v] = 0.f;

    gemm128_loop(A, CH, B, CH, smbase, tid, qrow, qcol, wm, wn, CH / BK, acc);

    // ---- fused block-softmax epilogue ----
    float* redm = (float*)smraw + (S2RED >> 2);
    float* redl = redm + 512;

    float mrow[4][2];
    #pragma unroll
    for (int mt = 0; mt < 4; mt++)
        #pragma unroll
        for (int h = 0; h < 2; h++) {
            float v = -1e30f;
            #pragma unroll
            for (int nt = 0; nt < 4; nt++)
                v = fmaxf(v, fmaxf(acc[mt][nt][h * 2], acc[mt][nt][h * 2 + 1]));
            v = fmaxf(v, __shfl_xor_sync(0xffffffffu, v, 1));
            v = fmaxf(v, __shfl_xor_sync(0xffffffffu, v, 2));
            mrow[mt][h] = v;
            if (qcol == 0)
                redm[wn * 128 + wm * 64 + mt * 16 + qrow + h * 8] = v;
        }
    __syncthreads();
    #pragma unroll
    for (int mt = 0; mt < 4; mt++)
        #pragma unroll
        for (int h = 0; h < 2; h++) {
            int lr = wm * 64 + mt * 16 + qrow + h * 8;
            mrow[mt][h] = fmaxf(fmaxf(redm[lr], redm[128 + lr]),
                                fmaxf(redm[256 + lr], redm[384 + lr]));
        }

    __half* Pb = g_ah + (size_t)z * NPIX * NPIX;
    float ls[4][2] = {{0.f,0.f},{0.f,0.f},{0.f,0.f},{0.f,0.f}};
    #pragma unroll
    for (int nt = 0; nt < 4; nt++) {
        int colg = bn + wn * 32 + nt * 8 + qcol * 2;
        #pragma unroll
        for (int mt = 0; mt < 4; mt++) {
            int r0 = bm + wm * 64 + mt * 16 + qrow;
            float p0 = __expf(acc[mt][nt][0] - mrow[mt][0]);
            float p1 = __expf(acc[mt][nt][1] - mrow[mt][0]);
            float p2 = __expf(acc[mt][nt][2] - mrow[mt][1]);
            float p3 = __expf(acc[mt][nt][3] - mrow[mt][1]);
            ls[mt][0] += p0 + p1;
            ls[mt][1] += p2 + p3;
            *(__half2*)&Pb[(size_t)r0 * NPIX + colg]       = __floats2half2_rn(p0, p1);
            *(__half2*)&Pb[(size_t)(r0 + 8) * NPIX + colg] = __floats2half2_rn(p2, p3);
        }
    }
    #pragma unroll
    for (int mt = 0; mt < 4; mt++)
        #pragma unroll
        for (int h = 0; h < 2; h++) {
            float v = ls[mt][h];
            v += __shfl_xor_sync(0xffffffffu, v, 1);
            v += __shfl_xor_sync(0xffffffffu, v, 2);
            if (qcol == 0)
                redl[wn * 128 + wm * 64 + mt * 16 + qrow + h * 8] = v;
        }
    __syncthreads();
    if (wn == 0 && qcol == 0) {
        float* BM_ = g_bm + ((size_t)z * NBLK + jb) * NPIX + bm;
        float* BL_ = g_bl + ((size_t)z * NBLK + jb) * NPIX + bm;
        #pragma unroll
        for (int mt = 0; mt < 4; mt++)
            #pragma unroll
            for (int h = 0; h < 2; h++) {
                int lr = wm * 64 + mt * 16 + qrow + h * 8;
                BM_[lr] = mrow[mt][h];
                BL_[lr] = redl[lr] + redl[128 + lr] + redl[256 + lr] + redl[384 + lr];
            }
    }
}

// ---------------------------------------------------------------------------
// Row stats: scale[z][jb][i] = exp(m_b - m_g) / tot
// ---------------------------------------------------------------------------
__global__ __launch_bounds__(256) void rowstats_kernel()
{
    int t = blockIdx.x * 256 + threadIdx.x;
    int z = t >> 12, i = t & (NPIX - 1);
    size_t base = (size_t)z * NBLK * NPIX + i;

    float mv[NBLK];
    float mg = -1e30f;
    #pragma unroll
    for (int jb = 0; jb < NBLK; jb++) {
        mv[jb] = g_bm[base + (size_t)jb * NPIX];
        mg = fmaxf(mg, mv[jb]);
    }
    float tot = 0.f;
    #pragma unroll
    for (int jb = 0; jb < NBLK; jb++)
        tot += g_bl[base + (size_t)jb * NPIX] * __expf(mv[jb] - mg);
    float inv = 1.0f / tot;
    #pragma unroll
    for (int jb = 0; jb < NBLK; jb++)
        g_sc[base + (size_t)jb * NPIX] = __expf(mv[jb] - mg) * inv;
}

// ---------------------------------------------------------------------------
// AV GEMM with in-loop normalization (R12-proven).
// ---------------------------------------------------------------------------
#define AVTILE 10240
#define AVBUF  (2 * AVTILE)
#define AVSC   (3 * AVBUF)
#define AVSMEM (AVSC + NBLK * 128 * 4)

__device__ __forceinline__ void load_av2(const __half* __restrict__ Ag,
                                         const __half* __restrict__ Bg,
                                         uint32_t sbase, int tid) {
    #pragma unroll
    for (int i = 0; i < 2; i++) {
        int t = i * 256 + tid;
        int row = t >> 2, q = t & 3;
        cp16(sbase + (uint32_t)(row * 80 + q * 16), Ag + (size_t)row * NPIX + q * 8);
    }
    #pragma unroll
    for (int i = 0; i < 2; i++) {
        int t = i * 256 + tid;
        int row = t >> 2, q = t & 3;
        cp16(sbase + AVTILE + (uint32_t)(row * 80 + q * 16), Bg + (size_t)row * NPIX + q * 8);
    }
}

__global__ __launch_bounds__(256, 2)
void av3_kernel(const __half* __restrict__ A,
                const __half* __restrict__ B,
                float* __restrict__ D)
{
    extern __shared__ __align__(16) uint32_t smraw[];
    const uint32_t smbase = smem_u32(smraw);
    const int tid = threadIdx.x;
    const int lane = tid & 31, wid = tid >> 5;
    const int wm = wid >> 2, wn = wid & 3;
    const int z = blockIdx.z;
    const int bm = blockIdx.y * 128, bn = blockIdx.x * 128;

    A += (size_t)z * CH * NPIX + (size_t)bm * NPIX;
    B += (size_t)z * NPIX * NPIX + (size_t)bn * NPIX;
    D += (size_t)z * CH * NPIX;

    {
        const float* SC = g_sc + (size_t)z * NBLK * NPIX + bn;
        float* sdst = (float*)smraw + (AVSC >> 2);
        #pragma unroll
        for (int t = 0; t < 16; t++) {
            int task = t * 256 + tid;
            int jbb = task >> 7, ii = task & 127;
            sdst[jbb * 128 + ii] = SC[(size_t)jbb * NPIX + ii];
        }
    }

    float acc[4][4][4];
    #pragma unroll
    for (int i = 0; i < 4; i++)
        #pragma unroll
        for (int j = 0; j < 4; j++)
            #pragma unroll
            for (int v = 0; v < 4; v++) acc[i][j][v] = 0.f;

    const int qrow = lane >> 2, qcol = lane & 3;
    const int S = NPIX / BK;   // 128

    load_av2(A, B, smbase, tid);
    CP_COMMIT();
    load_av2(A + BK, B + BK, smbase + AVBUF, tid);
    CP_COMMIT();

    uint32_t sreg[4];

    #pragma unroll 1
    for (int s = 0; s < S; s++) {
        CP_WAIT1();
        __syncthreads();
        if (s + 2 < S)
            load_av2(A + (s + 2) * BK, B + (s + 2) * BK,
                     smbase + (uint32_t)((s + 2) % 3) * AVBUF, tid);
        CP_COMMIT();

        if ((s & 3) == 0) {
            int jbb = s >> 2;
            #pragma unroll
            for (int nt = 0; nt < 4; nt++) {
                int cr = wn * 32 + nt * 8 + qrow;
                float sv;
                LDSF(sv, smbase + AVSC + (uint32_t)(jbb * 128 + cr) * 4);
                __half2 h2 = __float2half2_rn(sv);
                sreg[nt] = *(uint32_t*)&h2;
            }
        }

        uint32_t sa = smbase + (uint32_t)(s % 3) * AVBUF;
        uint32_t sb = sa + AVTILE;
        #pragma unroll
        for (int ks = 0; ks < 2; ks++) {
            const int kc = ks * 16 + qcol * 2;
            uint32_t af[4][4];
            #pragma unroll
            for (int mt = 0; mt < 4; mt++) {
                int r = wm * 64 + mt * 16 + qrow;
                LDS32(af[mt][0], sa + (uint32_t)(r * 80 + kc * 2));
                LDS32(af[mt][1], sa + (uint32_t)((r + 8) * 80 + kc * 2));
                LDS32(af[mt][2], sa + (uint32_t)(r * 80 + (kc + 8) * 2));
                LDS32(af[mt][3], sa + (uint32_t)((r + 8) * 80 + (kc + 8) * 2));
            }
            #pragma unroll
            for (int nt = 0; nt < 4; nt++) {
                int cr = wn * 32 + nt * 8 + qrow;
                uint32_t b0, b1;
                LDS32(b0, sb + (uint32_t)(cr * 80 + kc * 2));
                LDS32(b1, sb + (uint32_t)(cr * 80 + (kc + 8) * 2));
                __half2 hb0 = __hmul2(*(__half2*)&b0, *(__half2*)&sreg[nt]);
                __half2 hb1 = __hmul2(*(__half2*)&b1, *(__half2*)&sreg[nt]);
                b0 = *(uint32_t*)&hb0;
                b1 = *(uint32_t*)&hb1;
                #pragma unroll
                for (int mt = 0; mt < 4; mt++)
                    MMAH(acc[mt][nt], af[mt], b0, b1);
            }
        }
    }

    #pragma unroll
    for (int nt = 0; nt < 4; nt++) {
        int col = bn + wn * 32 + nt * 8 + qcol * 2;
        #pragma unroll
        for (int mt = 0; mt < 4; mt++) {
            int r0 = bm + wm * 64 + mt * 16 + qrow;
            *(float2*)&D[(size_t)r0 * NPIX + col] =
                make_float2(acc[mt][nt][0], acc[mt][nt][1]);
            *(float2*)&D[(size_t)(r0 + 8) * NPIX + col] =
                make_float2(acc[mt][nt][2], acc[mt][nt][3]);
        }
    }
}

// ---------------------------------------------------------------------------
// Packing kernels
// ---------------------------------------------------------------------------
__global__ __launch_bounds__(256) void pack_w_kernel(
    const float* __restrict__ wq, const float* __restrict__ wk,
    const float* __restrict__ wv)
{
    int i = blockIdx.x * 256 + threadIdx.x;
    g_wp[i]               = pack_split(wq[i]);
    g_wp[CH * CH + i]     = pack_split(wk[i]);
    g_wp[2 * CH * CH + i] = pack_split(wv[i]);
}

__global__ __launch_bounds__(256) void pack_xt_kernel(const float* __restrict__ x)
{
    __shared__ float t[32][33];
    const int b = blockIdx.z;
    const int n0 = blockIdx.x * 32, c0 = blockIdx.y * 32;
    const int tx = threadIdx.x, ty = threadIdx.y;
    const float* xb = x + (size_t)b * CH * NPIX;
    #pragma unroll
    for (int i = 0; i < 4; i++)
        t[ty * 4 + i][tx] = xb[(size_t)(c0 + ty * 4 + i) * NPIX + n0 + tx];
    __syncthreads();
    uint32_t* xt = g_xt + (size_t)b * NPIX * CH;
    #pragma unroll
    for (int i = 0; i < 4; i++)
        xt[(size_t)(n0 + ty * 4 + i) * CH + c0 + tx] = pack_split(t[tx][ty * 4 + i]);
}

// ---------------------------------------------------------------------------
extern "C" void kernel_launch(void* const* d_in, const int* in_sizes, int n_in,
                              void* d_out, int out_size)
{
    const float* x  = (const float*)d_in[0];
    const float* wq = (const float*)d_in[1];
    const float* bq = (const float*)d_in[2];
    const float* wk = (const float*)d_in[3];
    const float* bk = (const float*)d_in[4];
    const float* wv = (const float*)d_in[5];
    const float* bv = (const float*)d_in[6];
    float* out = (float*)d_out;

    void *pvh, *pah;
    cudaGetSymbolAddress(&pvh, g_vh);
    cudaGetSymbolAddress(&pah, g_ah);
    __half* vh = (__half*)pvh;
    __half* ah = (__half*)pah;

    cudaFuncSetAttribute(qk2_kernel,     cudaFuncAttributeMaxDynamicSharedMemorySize, S2SMEM);
    cudaFuncSetAttribute(v2_kernel,      cudaFuncAttributeMaxDynamicSharedMemorySize, S2SMEM);
    cudaFuncSetAttribute(scores2_kernel, cudaFuncAttributeMaxDynamicSharedMemorySize, S2SMEM);
    cudaFuncSetAttribute(av3_kernel,     cudaFuncAttributeMaxDynamicSharedMemorySize, AVSMEM);

    pack_w_kernel<<<CH * CH / 256, 256>>>(wq, wk, wv);
    pack_xt_kernel<<<dim3(NPIX / 32, CH / 32, BATCH), dim3(32, 8)>>>(x);

    // Q^T and K^T projections merged (z = b*2 + which), 2 CTAs/SM
    qk2_kernel<<<dim3(CH / 128, NPIX / 128, BATCH * 2), 256, S2SMEM>>>(bq, bk);
    // V[c][n] fp16 single plane, 2 CTAs/SM
    v2_kernel<<<dim3(NPIX / 128, CH / 128, BATCH), 256, S2SMEM>>>(bv);
    // scores + fused block softmax -> p, m_block, l_block
    scores2_kernel<<<dim3(NPIX / 128, NPIX / 128, BATCH), 256, S2SMEM>>>();
    // per-row global stats -> scale
    rowstats_kernel<<<BATCH * NPIX / 256, 256>>>();
    // out[c][i] = sum_j V[c][j] * p[i][j] * scale  (norm fused into AV)
    av3_kernel<<<dim3(NPIX / 128, CH / 128, BATCH), 256, AVSMEM>>>(vh, ah, out);
}